// round 12
// baseline (speedup 1.0000x reference)
#include <cuda_runtime.h>
#include <math.h>

#define NPTS 4096
#define BATCH 4
#define CCH 128
#define KNN 10
#define RTOT (BATCH * NPTS)

typedef unsigned long long u64;
typedef unsigned int u32;

// ---------------- scratch (device globals) ----------------
__device__ float g_Wc1[256 * 128];
__device__ float g_Wc2[512 * 128];
__device__ float g_UV1[BATCH * 256 * NPTS];
__device__ float g_UV2[BATCH * 512 * NPTS];
__device__ float g_xcat[BATCH * 512 * NPTS];
__device__ float g_y3[BATCH * CCH * NPTS];
__device__ int   g_idt[BATCH * KNN * NPTS];        // transposed: [b][k][n]
__device__ float g_kpd[BATCH * 4 * NPTS * KNN];
__device__ int   g_kpi[BATCH * 4 * NPTS * KNN];

// ---------------- tf32 helpers ----------------
__device__ __forceinline__ u32 cvt_tf32(float x) {
    u32 r; asm("cvt.rna.tf32.f32 %0, %1;" : "=r"(r) : "f"(x)); return r;
}
__device__ __forceinline__ void mma_tf32(float* c,
                                         u32 a0, u32 a1, u32 a2, u32 a3,
                                         u32 b0, u32 b1) {
    asm("mma.sync.aligned.m16n8k8.row.col.f32.tf32.tf32.f32 "
        "{%0,%1,%2,%3}, {%4,%5,%6,%7}, {%8,%9}, {%0,%1,%2,%3};"
        : "+f"(c[0]), "+f"(c[1]), "+f"(c[2]), "+f"(c[3])
        : "r"(a0), "r"(a1), "r"(a2), "r"(a3), "r"(b0), "r"(b1));
}

// ---------------- weight prep ----------------
__global__ void prep_w(const float* __restrict__ W1, const float* __restrict__ W2,
                       float* __restrict__ Wc1, float* __restrict__ Wc2) {
    int i = blockIdx.x * blockDim.x + threadIdx.x;
    if (i < 256 * 128) {
        int o = i / 128, c = i % 128;
        if (o < 128) Wc1[i] = W1[o * 256 + c] - W1[o * 256 + 128 + c];
        else         Wc1[i] = W1[(o - 128) * 256 + 128 + c];
    }
    if (i < 512 * 128) {
        int o = i / 128, c = i % 128;
        if (o < 256) Wc2[i] = W2[o * 256 + c] - W2[o * 256 + 128 + c];
        else         Wc2[i] = W2[(o - 256) * 256 + 128 + c];
    }
}

// ---------------- copy x0 halves into xcat rows [0,128) ----------------
__global__ void copy_x0(const float4* __restrict__ f, float4* __restrict__ xcat, int b0) {
    int i = blockIdx.x * blockDim.x + threadIdx.x;
    const int per = CCH * NPTS / 4;
    if (i >= 2 * per) return;
    int b = b0 + i / per, r = i % per;
    xcat[(size_t)b * (512 * NPTS / 4) + r] = f[(size_t)b * per + r];
}

// ---------------- KNN pass1 ----------------
__global__ void knn_part(const float* __restrict__ coords,
                         float* __restrict__ pd, int* __restrict__ pi) {
    int b = blockIdx.z, s = blockIdx.y;
    int n = blockIdx.x * 256 + threadIdx.x;
    const float* cb = coords + (size_t)b * 3 * NPTS;
    __shared__ float4 sc[1024];
    int base = s * 1024;
    for (int j = threadIdx.x; j < 1024; j += 256) {
        float x = cb[base + j], y = cb[NPTS + base + j], z = cb[2 * NPTS + base + j];
        sc[j] = make_float4(x, y, z, x * x + y * y + z * z);
    }
    __syncthreads();
    float qx = cb[n], qy = cb[NPTS + n], qz = cb[2 * NPTS + n];
    float qs = qx * qx + qy * qy + qz * qz;

    float dist[KNN]; int ind[KNN];
#pragma unroll
    for (int i = 0; i < KNN; i++) { dist[i] = 3.4e38f; ind[i] = 0x7fffffff; }

#pragma unroll 4
    for (int j = 0; j < 1024; j++) {
        int jj = base + j;
        float4 c = sc[j];
        float dot = qx * c.x + qy * c.y + qz * c.z;
        float d = fmaf(-2.f, dot, qs + c.w);
        d = fmaxf(d, 1e-12f);
        if (d < dist[KNN - 1] && jj != n) {
            dist[KNN - 1] = d; ind[KNN - 1] = jj;
#pragma unroll
            for (int i = KNN - 1; i > 0; i--) {
                bool sw = dist[i] < dist[i - 1];
                float td = sw ? dist[i - 1] : dist[i];
                int   ti = sw ? ind[i - 1]  : ind[i];
                dist[i - 1] = sw ? dist[i] : dist[i - 1];
                ind[i - 1]  = sw ? ind[i]  : ind[i - 1];
                dist[i] = td; ind[i] = ti;
            }
        }
    }
    size_t off = ((size_t)(b * 4 + s) * NPTS + n) * KNN;
#pragma unroll
    for (int i = 0; i < KNN; i++) { pd[off + i] = dist[i]; pi[off + i] = ind[i]; }
}

// ---------------- KNN merge ----------------
__global__ void knn_merge(const float* __restrict__ pd, const int* __restrict__ pi,
                          int* __restrict__ idt) {
    int t = blockIdx.x * 256 + threadIdx.x;
    if (t >= RTOT) return;
    int b = t >> 12, n = t & (NPTS - 1);
    const float* pdp[4]; const int* pip[4]; int pos[4] = {0, 0, 0, 0};
#pragma unroll
    for (int s = 0; s < 4; s++) {
        size_t off = ((size_t)(b * 4 + s) * NPTS + n) * KNN;
        pdp[s] = pd + off; pip[s] = pi + off;
    }
#pragma unroll
    for (int r = 0; r < KNN; r++) {
        float best = 3.5e38f; int bs = 0, bidx = 0x7fffffff;
#pragma unroll
        for (int s = 0; s < 4; s++) {
            float dv = pdp[s][pos[s]];
            int iv = pip[s][pos[s]];
            if (dv < best || (dv == best && iv < bidx)) { best = dv; bs = s; bidx = iv; }
        }
        idt[((size_t)b * KNN + r) * NPTS + n] = bidx;
        pos[bs]++;
    }
}

// ------------- GEMM tile v4: 128x128, tensor-core 3xTF32 mma.sync -------------
// O[m][n] = A[m][k] * X[k][n]; A row-major (lda), X row stride NPTS.
// 256 threads = 8 warps; warp covers m 32 x n 64.
__device__ __forceinline__ void gemm_tile(const float* __restrict__ A, int lda,
                                          const float* __restrict__ Xb,
                                          float* __restrict__ Ob, int Kd,
                                          int n0, int m0, bool accum) {
    const int NN = NPTS;
    __shared__ u32 Ah[16][132], Al[16][132];
    __shared__ u32 Xh[16][132], Xl[16][132];

    int tid = threadIdx.x;
    int warp = tid >> 5, lane = tid & 31;
    int g = lane >> 2, tg = lane & 3;
    int mw = (warp & 3) * 32;     // warp m-offset inside tile
    int nw = (warp >> 2) * 64;    // warp n-offset inside tile

    float c[2][8][4];
#pragma unroll
    for (int ms = 0; ms < 2; ms++)
#pragma unroll
        for (int ns = 0; ns < 8; ns++)
#pragma unroll
            for (int e = 0; e < 4; e++) c[ms][ns][e] = 0.f;

    for (int k0 = 0; k0 < Kd; k0 += 16) {
        // stage A (transposed, hi/lo split)
#pragma unroll
        for (int t = 0; t < 2; t++) {
            int f = tid * 2 + t;
            int rr = f >> 2, kc = (f & 3) * 4;
            float4 v = *(const float4*)&A[(size_t)(m0 + rr) * lda + k0 + kc];
            float vv[4] = {v.x, v.y, v.z, v.w};
#pragma unroll
            for (int e = 0; e < 4; e++) {
                u32 h = cvt_tf32(vv[e]);
                u32 l = cvt_tf32(vv[e] - __uint_as_float(h));
                Ah[kc + e][rr] = h;
                Al[kc + e][rr] = l;
            }
        }
        // stage X (row-major, hi/lo split, vectorized stores)
#pragma unroll
        for (int t = 0; t < 2; t++) {
            int f = tid * 2 + t;
            int kk = f >> 5, nc = (f & 31) * 4;
            float4 v = *(const float4*)&Xb[(size_t)(k0 + kk) * NN + n0 + nc];
            float vv[4] = {v.x, v.y, v.z, v.w};
            uint4 hv, lv;
            u32* hp = (u32*)&hv; u32* lp = (u32*)&lv;
#pragma unroll
            for (int e = 0; e < 4; e++) {
                u32 h = cvt_tf32(vv[e]);
                hp[e] = h;
                lp[e] = cvt_tf32(vv[e] - __uint_as_float(h));
            }
            *(uint4*)&Xh[kk][nc] = hv;
            *(uint4*)&Xl[kk][nc] = lv;
        }
        __syncthreads();

#pragma unroll
        for (int ks = 0; ks < 16; ks += 8) {
            // A fragments for 2 m-subtiles (hi + lo)
            u32 ah[2][4], al[2][4];
#pragma unroll
            for (int ms = 0; ms < 2; ms++) {
                int mr = mw + ms * 16;
                ah[ms][0] = Ah[ks + tg][mr + g];
                ah[ms][1] = Ah[ks + tg][mr + g + 8];
                ah[ms][2] = Ah[ks + tg + 4][mr + g];
                ah[ms][3] = Ah[ks + tg + 4][mr + g + 8];
                al[ms][0] = Al[ks + tg][mr + g];
                al[ms][1] = Al[ks + tg][mr + g + 8];
                al[ms][2] = Al[ks + tg + 4][mr + g];
                al[ms][3] = Al[ks + tg + 4][mr + g + 8];
            }
#pragma unroll
            for (int ns = 0; ns < 8; ns++) {
                int ncol = nw + ns * 8 + g;
                u32 b0h = Xh[ks + tg][ncol];
                u32 b1h = Xh[ks + tg + 4][ncol];
                u32 b0l = Xl[ks + tg][ncol];
                u32 b1l = Xl[ks + tg + 4][ncol];
#pragma unroll
                for (int ms = 0; ms < 2; ms++) {
                    mma_tf32(c[ms][ns], ah[ms][0], ah[ms][1], ah[ms][2], ah[ms][3], b0h, b1h);
                    mma_tf32(c[ms][ns], ah[ms][0], ah[ms][1], ah[ms][2], ah[ms][3], b0l, b1l);
                    mma_tf32(c[ms][ns], al[ms][0], al[ms][1], al[ms][2], al[ms][3], b0h, b1h);
                }
            }
        }
        __syncthreads();
    }

    // epilogue: c[ms][ns] -> O
#pragma unroll
    for (int ms = 0; ms < 2; ms++) {
#pragma unroll
        for (int ns = 0; ns < 8; ns++) {
            int m = m0 + mw + ms * 16 + g;
            int n = n0 + nw + ns * 8 + 2 * tg;
            float* p0 = Ob + (size_t)m * NN + n;
            float* p1 = Ob + (size_t)(m + 8) * NN + n;
            float2 v0 = make_float2(c[ms][ns][0], c[ms][ns][1]);
            float2 v1 = make_float2(c[ms][ns][2], c[ms][ns][3]);
            if (accum) {
                float2 o0 = *(const float2*)p0;
                float2 o1 = *(const float2*)p1;
                v0.x += o0.x; v0.y += o0.y;
                v1.x += o1.x; v1.y += o1.y;
            }
            *(float2*)p0 = v0;
            *(float2*)p1 = v1;
        }
    }
}

// ---------------- generic GEMM launcher kernel ----------------
__global__ __launch_bounds__(256)
void gemm_full(const float* __restrict__ A, int lda,
               const float* __restrict__ X,
               float* __restrict__ O, int orows, int Kd, int accum) {
    int n0 = blockIdx.x * 128, m0 = blockIdx.y * 128, b = blockIdx.z;
    gemm_tile(A, lda, X + (size_t)b * 512 * NPTS,
              O + (size_t)b * orows * NPTS, Kd, n0, m0, accum != 0);
}

// ---------------- EdgeConv epilogue ----------------
__global__ void edge_epilogue(const float* __restrict__ UV, const int* __restrict__ idt,
                              float* __restrict__ xcat, int Ch, int rowsPerBatch, int outRow0) {
    int o = blockIdx.x, b = blockIdx.y, tid = threadIdx.x;
    const float* U = UV + ((size_t)b * rowsPerBatch + o) * NPTS;
    const float* V = UV + ((size_t)b * rowsPerBatch + Ch + o) * NPTS;
    const int* it = idt + (size_t)b * KNN * NPTS;
    float* op = xcat + ((size_t)b * 512 + outRow0 + o) * NPTS;

    __shared__ float  sV[NPTS];
    __shared__ float  smax[NPTS];
    __shared__ double sred[256], s2red[256];
    __shared__ float  smu, srstd;

    {
        const float4* V4 = (const float4*)V;
        float4* sV4 = (float4*)sV;
        sV4[tid] = V4[tid];
        sV4[tid + 256] = V4[tid + 256];
        sV4[tid + 512] = V4[tid + 512];
        sV4[tid + 768] = V4[tid + 768];
    }
    __syncthreads();

    double s = 0.0, s2 = 0.0;
    for (int n = tid; n < NPTS / 2; n += 256) {
        int n2 = n + NPTS / 2;
        float ua = U[n], ub = U[n2];
        float ma = -3.4e38f, mb = -3.4e38f;
        float psa = 0.f, pqa = 0.f, psb = 0.f, pqb = 0.f;
#pragma unroll
        for (int kk = 0; kk < KNN; kk++) {
            int ja = it[kk * NPTS + n];
            int jb = it[kk * NPTS + n2];
            float ya = ua + sV[ja];
            float yb = ub + sV[jb];
            ma = fmaxf(ma, ya); psa += ya; pqa += ya * ya;
            mb = fmaxf(mb, yb); psb += yb; pqb += yb * yb;
        }
        smax[n] = ma; smax[n2] = mb;
        s += (double)(psa) + (double)(psb);
        s2 += (double)(pqa) + (double)(pqb);
    }
    sred[tid] = s; s2red[tid] = s2;
    __syncthreads();
    for (int st = 128; st > 0; st >>= 1) {
        if (tid < st) { sred[tid] += sred[tid + st]; s2red[tid] += s2red[tid + st]; }
        __syncthreads();
    }
    if (tid == 0) {
        double cnt = (double)NPTS * KNN;
        double mu  = sred[0] / cnt;
        double var = s2red[0] / cnt - mu * mu;
        smu   = (float)mu;
        srstd = (float)(1.0 / sqrt(var + 1e-5));
    }
    __syncthreads();
    float mu = smu, r = srstd;
    for (int n = tid; n < NPTS; n += 256) {
        float v = (smax[n] - mu) * r;
        op[n] = v >= 0.f ? v : 0.2f * v;
    }
}

// ---------------- final instance-norm (over N) + lrelu ----------------
__global__ void norm_epilogue(const float* __restrict__ Y, float* __restrict__ out) {
    int o = blockIdx.x, b = blockIdx.y, tid = threadIdx.x;
    const float* y = Y + ((size_t)b * CCH + o) * NPTS;
    float* op = out + ((size_t)b * CCH + o) * NPTS;

    __shared__ double sred[256], s2red[256];
    __shared__ float  smu, srstd;

    double s = 0.0, s2 = 0.0;
    for (int n = tid; n < NPTS; n += 256) {
        float v = y[n];
        s += (double)v; s2 += (double)v * (double)v;
    }
    sred[tid] = s; s2red[tid] = s2;
    __syncthreads();
    for (int st = 128; st > 0; st >>= 1) {
        if (tid < st) { sred[tid] += sred[tid + st]; s2red[tid] += s2red[tid + st]; }
        __syncthreads();
    }
    if (tid == 0) {
        double cnt = (double)NPTS;
        double mu  = sred[0] / cnt;
        double var = s2red[0] / cnt - mu * mu;
        smu   = (float)mu;
        srstd = (float)(1.0 / sqrt(var + 1e-5));
    }
    __syncthreads();
    float mu = smu, r = srstd;
    for (int n = tid; n < NPTS; n += 256) {
        float v = (y[n] - mu) * r;
        op[n] = v >= 0.f ? v : 0.2f * v;
    }
}

// ---------------- launch: graph-forked parallel branches (static handles) ----------------
extern "C" void kernel_launch(void* const* d_in, const int* in_sizes, int n_in,
                              void* d_out, int out_size) {
    const float* coords = (const float*)d_in[0];
    const float* feats  = (const float*)d_in[1];
    const float* W1     = (const float*)d_in[2];
    const float* W2     = (const float*)d_in[3];
    const float* W3     = (const float*)d_in[4];
    float* out = (float*)d_out;

    float *Wc1, *Wc2, *UV1, *UV2, *xcat, *y3, *kpd;
    int *idt, *kpi;
    cudaGetSymbolAddress((void**)&Wc1,  g_Wc1);
    cudaGetSymbolAddress((void**)&Wc2,  g_Wc2);
    cudaGetSymbolAddress((void**)&UV1,  g_UV1);
    cudaGetSymbolAddress((void**)&UV2,  g_UV2);
    cudaGetSymbolAddress((void**)&xcat, g_xcat);
    cudaGetSymbolAddress((void**)&y3,   g_y3);
    cudaGetSymbolAddress((void**)&idt,  g_idt);
    cudaGetSymbolAddress((void**)&kpd,  g_kpd);
    cudaGetSymbolAddress((void**)&kpi,  g_kpi);

    // Streams/events created EXACTLY ONCE (first call, pre-capture) and never
    // destroyed -> post-teardown free memory matches the pre-capture baseline.
    static cudaStream_t sB = nullptr, sC = nullptr;
    static cudaEvent_t eF1, eB, eF2, eC;
    static bool inited = false;
    if (!inited) {
        cudaStreamCreateWithFlags(&sB, cudaStreamNonBlocking);
        cudaStreamCreateWithFlags(&sC, cudaStreamNonBlocking);
        cudaEventCreateWithFlags(&eF1, cudaEventDisableTiming);
        cudaEventCreateWithFlags(&eB,  cudaEventDisableTiming);
        cudaEventCreateWithFlags(&eF2, cudaEventDisableTiming);
        cudaEventCreateWithFlags(&eC,  cudaEventDisableTiming);
        inited = true;
    }

    const int perHalf = 2 * CCH * NPTS / 4;

    // ---- fork branch B off the main stream ----
    cudaEventRecord(eF1, 0);
    cudaStreamWaitEvent(sB, eF1, 0);

    // branch B submissions first (so the new MMA gemm is the 4th kernel = profiled)
    prep_w<<<256, 256, 0, sB>>>(W1, W2, Wc1, Wc2);
    copy_x0<<<(perHalf + 255) / 256, 256, 0, sB>>>((const float4*)feats, (float4*)xcat, 0);
    copy_x0<<<(perHalf + 255) / 256, 256, 0, sB>>>((const float4*)feats, (float4*)xcat, 2);
    gemm_full<<<dim3(32, 2, BATCH), 256, 0, sB>>>(Wc1, 128, xcat, UV1, 256, 128, 0);
    gemm_full<<<dim3(32, 1, BATCH), 256, 0, sB>>>(W3, 512, xcat, y3, 128, 128, 0);   // y3 = W3a@x0

    // main stream: KNN chain (critical path, concurrent with branch B)
    knn_part<<<dim3(NPTS / 256, 4, BATCH), 256>>>(coords, kpd, kpi);
    knn_merge<<<RTOT / 256, 256>>>(kpd, kpi, idt);

    // join B -> main
    cudaEventRecord(eB, sB);
    cudaStreamWaitEvent(0, eB, 0);

    // main: edge1 (needs idt + UV1)
    edge_epilogue<<<dim3(128, BATCH), 256>>>(UV1, idt, xcat, 128, 256, 128);

    // ---- fork branch C (gemm3b needs x1 only) ----
    cudaEventRecord(eF2, 0);
    cudaStreamWaitEvent(sC, eF2, 0);
    gemm_full<<<dim3(32, 1, BATCH), 256, 0, sC>>>(W3 + 128, 512, xcat + (size_t)128 * NPTS,
                                                  y3, 128, 128, 1);  // y3 += W3b@x1

    // main: gemm2 -> edge2
    gemm_full<<<dim3(32, 4, BATCH), 256>>>(Wc2, 128, xcat + (size_t)128 * NPTS, UV2, 512, 128, 0);
    edge_epilogue<<<dim3(256, BATCH), 256>>>(UV2, idt, xcat, 256, 512, 256);

    // join C -> main
    cudaEventRecord(eC, sC);
    cudaStreamWaitEvent(0, eC, 0);

    // main: gemm3c (y3 += W3c@x2, K=256) -> final norm
    gemm_full<<<dim3(32, 1, BATCH), 256>>>(W3 + 256, 512, xcat + (size_t)256 * NPTS, y3, 128, 256, 1);
    norm_epilogue<<<dim3(128, BATCH), 256>>>(y3, out);
}

// round 13
// speedup vs baseline: 1.1117x; 1.1117x over previous
#include <cuda_runtime.h>
#include <math.h>

#define NPTS 4096
#define BATCH 4
#define CCH 128
#define KNN 10
#define RTOT (BATCH * NPTS)
#define NSLICE 2
#define SLICE 2048

typedef unsigned long long u64;

// ---------------- scratch (device globals) ----------------
__device__ float g_Wc1[256 * 128];
__device__ float g_Wc2[512 * 128];
__device__ float g_UV1[BATCH * 256 * NPTS];
__device__ float g_UV2[BATCH * 512 * NPTS];
__device__ float g_xcat[BATCH * 512 * NPTS];
__device__ float g_y3[BATCH * CCH * NPTS];
__device__ int   g_idt[BATCH * KNN * NPTS];        // transposed: [b][k][n]
__device__ float g_kpd[BATCH * NSLICE * NPTS * KNN];
__device__ int   g_kpi[BATCH * NSLICE * NPTS * KNN];

// ---------------- f32x2 helpers ----------------
__device__ __forceinline__ u64 bcast2(float a) {
    u64 r; asm("mov.b64 %0, {%1, %1};" : "=l"(r) : "f"(a)); return r;
}
__device__ __forceinline__ void fma2(u64& d, u64 a, u64 b) {
    asm("fma.rn.f32x2 %0, %1, %2, %0;" : "+l"(d) : "l"(a), "l"(b));
}

// ---------------- weight prep ----------------
__global__ void prep_w(const float* __restrict__ W1, const float* __restrict__ W2,
                       float* __restrict__ Wc1, float* __restrict__ Wc2) {
    int i = blockIdx.x * blockDim.x + threadIdx.x;
    if (i < 256 * 128) {
        int o = i / 128, c = i % 128;
        if (o < 128) Wc1[i] = W1[o * 256 + c] - W1[o * 256 + 128 + c];
        else         Wc1[i] = W1[(o - 128) * 256 + 128 + c];
    }
    if (i < 512 * 128) {
        int o = i / 128, c = i % 128;
        if (o < 256) Wc2[i] = W2[o * 256 + c] - W2[o * 256 + 128 + c];
        else         Wc2[i] = W2[(o - 256) * 256 + 128 + c];
    }
}

// ---------------- copy x0 halves into xcat rows [0,128) ----------------
__global__ void copy_x0(const float4* __restrict__ f, float4* __restrict__ xcat, int b0) {
    int i = blockIdx.x * blockDim.x + threadIdx.x;
    const int per = CCH * NPTS / 4;
    if (i >= 2 * per) return;
    int b = b0 + i / per, r = i % per;
    xcat[(size_t)b * (512 * NPTS / 4) + r] = f[(size_t)b * per + r];
}

// ---------------- KNN pass1: 2 slices of 2048, 128-thread blocks ----------------
__global__ __launch_bounds__(128)
void knn_part(const float* __restrict__ coords,
              float* __restrict__ pd, int* __restrict__ pi) {
    int b = blockIdx.z, s = blockIdx.y;
    int n = blockIdx.x * 128 + threadIdx.x;
    const float* cb = coords + (size_t)b * 3 * NPTS;
    __shared__ float4 sc[SLICE];                 // 32 KB
    int base = s * SLICE;
    for (int j = threadIdx.x; j < SLICE; j += 128) {
        float x = cb[base + j], y = cb[NPTS + base + j], z = cb[2 * NPTS + base + j];
        sc[j] = make_float4(x, y, z, x * x + y * y + z * z);
    }
    __syncthreads();
    float qx = cb[n], qy = cb[NPTS + n], qz = cb[2 * NPTS + n];
    float qs = qx * qx + qy * qy + qz * qz;

    float dist[KNN]; int ind[KNN];
#pragma unroll
    for (int i = 0; i < KNN; i++) { dist[i] = 3.4e38f; ind[i] = 0x7fffffff; }

#pragma unroll 4
    for (int j = 0; j < SLICE; j++) {
        int jj = base + j;
        float4 c = sc[j];                        // LDS.128 broadcast
        float dot = qx * c.x + qy * c.y + qz * c.z;
        float d = fmaf(-2.f, dot, qs + c.w);
        d = fmaxf(d, 1e-12f);
        if (d < dist[KNN - 1] && jj != n) {
            dist[KNN - 1] = d; ind[KNN - 1] = jj;
#pragma unroll
            for (int i = KNN - 1; i > 0; i--) {
                bool sw = dist[i] < dist[i - 1];
                float td = sw ? dist[i - 1] : dist[i];
                int   ti = sw ? ind[i - 1]  : ind[i];
                dist[i - 1] = sw ? dist[i] : dist[i - 1];
                ind[i - 1]  = sw ? ind[i]  : ind[i - 1];
                dist[i] = td; ind[i] = ti;
            }
        }
    }
    size_t off = ((size_t)(b * NSLICE + s) * NPTS + n) * KNN;
#pragma unroll
    for (int i = 0; i < KNN; i++) { pd[off + i] = dist[i]; pi[off + i] = ind[i]; }
}

// ---------------- KNN merge: 2 sorted lists -> final 10, transposed output ----------------
__global__ void knn_merge(const float* __restrict__ pd, const int* __restrict__ pi,
                          int* __restrict__ idt) {
    int t = blockIdx.x * 256 + threadIdx.x;
    if (t >= RTOT) return;
    int b = t >> 12, n = t & (NPTS - 1);
    const float* pdp[NSLICE]; const int* pip[NSLICE]; int pos[NSLICE] = {0, 0};
#pragma unroll
    for (int s = 0; s < NSLICE; s++) {
        size_t off = ((size_t)(b * NSLICE + s) * NPTS + n) * KNN;
        pdp[s] = pd + off; pip[s] = pi + off;
    }
#pragma unroll
    for (int r = 0; r < KNN; r++) {
        float d0 = pdp[0][pos[0]], d1 = pdp[1][pos[1]];
        int i0 = pip[0][pos[0]], i1 = pip[1][pos[1]];
        bool take0 = (d0 < d1) || (d0 == d1 && i0 < i1);
        idt[((size_t)b * KNN + r) * NPTS + n] = take0 ? i0 : i1;
        if (take0) pos[0]++; else pos[1]++;
    }
}

// ---------------- GEMM tile (FFMA2, R11-proven): 128x128, 8x8 micro ----------------
__device__ __forceinline__ void gemm_tile(const float* __restrict__ A, int lda,
                                          const float* __restrict__ Xb,
                                          float* __restrict__ Ob, int Kd,
                                          int n0, int m0, bool accum) {
    const int NN = NPTS;
    __shared__ float As[16][132];
    __shared__ float Xs[16][132];

    int tid = threadIdx.x;
    int tr = tid & 15;
    int tm = tid >> 4;
    u64 acc2[8][4];
#pragma unroll
    for (int i = 0; i < 8; i++)
#pragma unroll
        for (int p = 0; p < 4; p++) acc2[i][p] = 0ull;

    for (int k0 = 0; k0 < Kd; k0 += 16) {
#pragma unroll
        for (int t = 0; t < 2; t++) {
            int f = tid * 2 + t;
            int rr = f >> 2, kc = (f & 3) * 4;
            float4 v = *(const float4*)&A[(size_t)(m0 + rr) * lda + k0 + kc];
            As[kc + 0][rr] = v.x; As[kc + 1][rr] = v.y;
            As[kc + 2][rr] = v.z; As[kc + 3][rr] = v.w;
        }
#pragma unroll
        for (int t = 0; t < 2; t++) {
            int f = tid * 2 + t;
            int kk = f >> 5, nc = (f & 31) * 4;
            *(float4*)&Xs[kk][nc] =
                *(const float4*)&Xb[(size_t)(k0 + kk) * NN + n0 + nc];
        }
        __syncthreads();
#pragma unroll
        for (int kk = 0; kk < 16; kk++) {
            float am[8];
            float4 x0 = *(const float4*)&Xs[kk][tr * 4];
            float4 x1 = *(const float4*)&Xs[kk][tr * 4 + 64];
            *(float4*)&am[0] = *(const float4*)&As[kk][tm * 4];
            *(float4*)&am[4] = *(const float4*)&As[kk][tm * 4 + 64];
            u64 xp[4];
            xp[0] = ((const u64*)&x0)[0]; xp[1] = ((const u64*)&x0)[1];
            xp[2] = ((const u64*)&x1)[0]; xp[3] = ((const u64*)&x1)[1];
#pragma unroll
            for (int i = 0; i < 8; i++) {
                u64 ab = bcast2(am[i]);
                fma2(acc2[i][0], ab, xp[0]);
                fma2(acc2[i][1], ab, xp[1]);
                fma2(acc2[i][2], ab, xp[2]);
                fma2(acc2[i][3], ab, xp[3]);
            }
        }
        __syncthreads();
    }
#pragma unroll
    for (int h = 0; h < 2; h++) {
#pragma unroll
        for (int i = 0; i < 4; i++) {
            int m = m0 + tm * 4 + i + h * 64;
            float* orow = Ob + (size_t)m * NN + n0;
            float4 v0, v1;
            ((u64*)&v0)[0] = acc2[h * 4 + i][0]; ((u64*)&v0)[1] = acc2[h * 4 + i][1];
            ((u64*)&v1)[0] = acc2[h * 4 + i][2]; ((u64*)&v1)[1] = acc2[h * 4 + i][3];
            if (accum) {
                float4 o0 = *(const float4*)&orow[tr * 4];
                float4 o1 = *(const float4*)&orow[tr * 4 + 64];
                v0.x += o0.x; v0.y += o0.y; v0.z += o0.z; v0.w += o0.w;
                v1.x += o1.x; v1.y += o1.y; v1.z += o1.z; v1.w += o1.w;
            }
            *(float4*)&orow[tr * 4] = v0;
            *(float4*)&orow[tr * 4 + 64] = v1;
        }
    }
}

// ---------------- generic GEMM launcher kernel ----------------
__global__ __launch_bounds__(256)
void gemm_full(const float* __restrict__ A, int lda,
               const float* __restrict__ X,
               float* __restrict__ O, int orows, int Kd, int accum) {
    int n0 = blockIdx.x * 128, m0 = blockIdx.y * 128, b = blockIdx.z;
    gemm_tile(A, lda, X + (size_t)b * 512 * NPTS,
              O + (size_t)b * orows * NPTS, Kd, n0, m0, accum != 0);
}

// ---------------- EdgeConv epilogue v4: 2 channels/block, register max ----------------
// grid (Ch/2, BATCH), 256 threads.
__global__ __launch_bounds__(256)
void edge_epilogue(const float* __restrict__ UV, const int* __restrict__ idt,
                   float* __restrict__ xcat, int Ch, int rowsPerBatch, int outRow0) {
    int o0 = blockIdx.x * 2, b = blockIdx.y, tid = threadIdx.x;
    const float* U0 = UV + ((size_t)b * rowsPerBatch + o0) * NPTS;
    const float* U1 = U0 + NPTS;
    const float* V0 = UV + ((size_t)b * rowsPerBatch + Ch + o0) * NPTS;
    const float* V1 = V0 + NPTS;
    const int* it = idt + (size_t)b * KNN * NPTS;
    float* op0 = xcat + ((size_t)b * 512 + outRow0 + o0) * NPTS;
    float* op1 = op0 + NPTS;

    __shared__ float  sV0[NPTS], sV1[NPTS];          // 32 KB
    __shared__ double sr0[256], sq0[256], sr1[256], sq1[256];   // 8 KB
    __shared__ float  smu0, srstd0, smu1, srstd1;

    {
        const float4* a = (const float4*)V0; float4* d0 = (float4*)sV0;
        const float4* c = (const float4*)V1; float4* d1 = (float4*)sV1;
#pragma unroll
        for (int i = 0; i < 4; i++) {
            d0[tid + i * 256] = a[tid + i * 256];
            d1[tid + i * 256] = c[tid + i * 256];
        }
    }
    __syncthreads();

    float m0[16], m1[16];
    double S0 = 0.0, Q0 = 0.0, S1 = 0.0, Q1 = 0.0;
#pragma unroll
    for (int itn = 0; itn < 16; itn++) {
        int n = tid + itn * 256;
        float u0 = U0[n], u1 = U1[n];
        float a0 = -3.4e38f, a1 = -3.4e38f;
        float p0 = 0.f, q0 = 0.f, p1 = 0.f, q1 = 0.f;
#pragma unroll
        for (int kk = 0; kk < KNN; kk++) {
            int j = it[kk * NPTS + n];           // one idx load serves both channels
            float y0 = u0 + sV0[j];
            float y1 = u1 + sV1[j];
            a0 = fmaxf(a0, y0); p0 += y0; q0 += y0 * y0;
            a1 = fmaxf(a1, y1); p1 += y1; q1 += y1 * y1;
        }
        m0[itn] = a0; m1[itn] = a1;
        S0 += (double)p0; Q0 += (double)q0;
        S1 += (double)p1; Q1 += (double)q1;
    }
    sr0[tid] = S0; sq0[tid] = Q0; sr1[tid] = S1; sq1[tid] = Q1;
    __syncthreads();
    for (int st = 128; st > 0; st >>= 1) {
        if (tid < st) {
            sr0[tid] += sr0[tid + st]; sq0[tid] += sq0[tid + st];
            sr1[tid] += sr1[tid + st]; sq1[tid] += sq1[tid + st];
        }
        __syncthreads();
    }
    if (tid == 0) {
        double cnt = (double)NPTS * KNN;
        double mu  = sr0[0] / cnt;
        double var = sq0[0] / cnt - mu * mu;
        smu0 = (float)mu; srstd0 = (float)(1.0 / sqrt(var + 1e-5));
        mu  = sr1[0] / cnt;
        var = sq1[0] / cnt - mu * mu;
        smu1 = (float)mu; srstd1 = (float)(1.0 / sqrt(var + 1e-5));
    }
    __syncthreads();
    float mu0 = smu0, r0 = srstd0, mu1 = smu1, r1 = srstd1;
#pragma unroll
    for (int itn = 0; itn < 16; itn++) {
        int n = tid + itn * 256;
        float v0 = (m0[itn] - mu0) * r0;
        float v1 = (m1[itn] - mu1) * r1;
        op0[n] = v0 >= 0.f ? v0 : 0.2f * v0;
        op1[n] = v1 >= 0.f ? v1 : 0.2f * v1;
    }
}

// ---------------- final instance-norm (over N) + lrelu ----------------
__global__ void norm_epilogue(const float* __restrict__ Y, float* __restrict__ out) {
    int o = blockIdx.x, b = blockIdx.y, tid = threadIdx.x;
    const float* y = Y + ((size_t)b * CCH + o) * NPTS;
    float* op = out + ((size_t)b * CCH + o) * NPTS;

    __shared__ double sred[256], s2red[256];
    __shared__ float  smu, srstd;

    double s = 0.0, s2 = 0.0;
    for (int n = tid; n < NPTS; n += 256) {
        float v = y[n];
        s += (double)v; s2 += (double)v * (double)v;
    }
    sred[tid] = s; s2red[tid] = s2;
    __syncthreads();
    for (int st = 128; st > 0; st >>= 1) {
        if (tid < st) { sred[tid] += sred[tid + st]; s2red[tid] += s2red[tid + st]; }
        __syncthreads();
    }
    if (tid == 0) {
        double cnt = (double)NPTS;
        double mu  = sred[0] / cnt;
        double var = s2red[0] / cnt - mu * mu;
        smu   = (float)mu;
        srstd = (float)(1.0 / sqrt(var + 1e-5));
    }
    __syncthreads();
    float mu = smu, r = srstd;
    for (int n = tid; n < NPTS; n += 256) {
        float v = (y[n] - mu) * r;
        op[n] = v >= 0.f ? v : 0.2f * v;
    }
}

// ---------------- launch: graph-forked parallel branches (static handles) ----------------
extern "C" void kernel_launch(void* const* d_in, const int* in_sizes, int n_in,
                              void* d_out, int out_size) {
    const float* coords = (const float*)d_in[0];
    const float* feats  = (const float*)d_in[1];
    const float* W1     = (const float*)d_in[2];
    const float* W2     = (const float*)d_in[3];
    const float* W3     = (const float*)d_in[4];
    float* out = (float*)d_out;

    float *Wc1, *Wc2, *UV1, *UV2, *xcat, *y3, *kpd;
    int *idt, *kpi;
    cudaGetSymbolAddress((void**)&Wc1,  g_Wc1);
    cudaGetSymbolAddress((void**)&Wc2,  g_Wc2);
    cudaGetSymbolAddress((void**)&UV1,  g_UV1);
    cudaGetSymbolAddress((void**)&UV2,  g_UV2);
    cudaGetSymbolAddress((void**)&xcat, g_xcat);
    cudaGetSymbolAddress((void**)&y3,   g_y3);
    cudaGetSymbolAddress((void**)&idt,  g_idt);
    cudaGetSymbolAddress((void**)&kpd,  g_kpd);
    cudaGetSymbolAddress((void**)&kpi,  g_kpi);

    // Streams/events created EXACTLY ONCE (first call, pre-capture) and never
    // destroyed -> post-teardown free memory matches the pre-capture baseline.
    static cudaStream_t sB = nullptr, sC = nullptr;
    static cudaEvent_t eF1, eB, eF2, eC;
    static bool inited = false;
    if (!inited) {
        cudaStreamCreateWithFlags(&sB, cudaStreamNonBlocking);
        cudaStreamCreateWithFlags(&sC, cudaStreamNonBlocking);
        cudaEventCreateWithFlags(&eF1, cudaEventDisableTiming);
        cudaEventCreateWithFlags(&eB,  cudaEventDisableTiming);
        cudaEventCreateWithFlags(&eF2, cudaEventDisableTiming);
        cudaEventCreateWithFlags(&eC,  cudaEventDisableTiming);
        inited = true;
    }

    const int perHalf = 2 * CCH * NPTS / 4;

    // ---- fork branch B off the main stream ----
    cudaEventRecord(eF1, 0);
    cudaStreamWaitEvent(sB, eF1, 0);

    // branch B prep first; knn_part is the 4th submitted kernel (profiled slot)
    prep_w<<<256, 256, 0, sB>>>(W1, W2, Wc1, Wc2);
    copy_x0<<<(perHalf + 255) / 256, 256, 0, sB>>>((const float4*)feats, (float4*)xcat, 0);
    copy_x0<<<(perHalf + 255) / 256, 256, 0, sB>>>((const float4*)feats, (float4*)xcat, 2);

    // main stream: KNN chain (critical path, concurrent with branch B)
    knn_part<<<dim3(NPTS / 128, NSLICE, BATCH), 128>>>(coords, kpd, kpi);

    // branch B: gemm1 + gemm3a
    gemm_full<<<dim3(32, 2, BATCH), 256, 0, sB>>>(Wc1, 128, xcat, UV1, 256, 128, 0);
    gemm_full<<<dim3(32, 1, BATCH), 256, 0, sB>>>(W3, 512, xcat, y3, 128, 128, 0);   // y3 = W3a@x0

    // main: merge
    knn_merge<<<RTOT / 256, 256>>>(kpd, kpi, idt);

    // join B -> main
    cudaEventRecord(eB, sB);
    cudaStreamWaitEvent(0, eB, 0);

    // main: edge1 (needs idt + UV1)
    edge_epilogue<<<dim3(128 / 2, BATCH), 256>>>(UV1, idt, xcat, 128, 256, 128);

    // ---- fork branch C (gemm3b needs x1 only) ----
    cudaEventRecord(eF2, 0);
    cudaStreamWaitEvent(sC, eF2, 0);
    gemm_full<<<dim3(32, 1, BATCH), 256, 0, sC>>>(W3 + 128, 512, xcat + (size_t)128 * NPTS,
                                                  y3, 128, 128, 1);  // y3 += W3b@x1

    // main: gemm2 -> edge2
    gemm_full<<<dim3(32, 4, BATCH), 256>>>(Wc2, 128, xcat + (size_t)128 * NPTS, UV2, 512, 128, 0);
    edge_epilogue<<<dim3(256 / 2, BATCH), 256>>>(UV2, idt, xcat, 256, 512, 256);

    // join C -> main
    cudaEventRecord(eC, sC);
    cudaStreamWaitEvent(0, eC, 0);

    // main: gemm3c (y3 += W3c@x2, K=256) -> final norm
    gemm_full<<<dim3(32, 1, BATCH), 256>>>(W3 + 256, 512, xcat + (size_t)256 * NPTS, y3, 128, 256, 1);
    norm_epilogue<<<dim3(128, BATCH), 256>>>(y3, out);
}

// round 14
// speedup vs baseline: 1.1255x; 1.0124x over previous
#include <cuda_runtime.h>
#include <math.h>

#define NPTS 4096
#define BATCH 4
#define CCH 128
#define KNN 10
#define RTOT (BATCH * NPTS)
#define NSLICE 2
#define SLICE 2048

typedef unsigned long long u64;

// ---------------- scratch (device globals) ----------------
__device__ float g_Wc1[256 * 128];
__device__ float g_Wc2[512 * 128];
__device__ float g_UV1[BATCH * 256 * NPTS];
__device__ float g_UV2[BATCH * 512 * NPTS];
__device__ float g_xcat[BATCH * 512 * NPTS];
__device__ float g_y3[BATCH * CCH * NPTS];
__device__ int   g_idt[BATCH * KNN * NPTS];        // transposed: [b][k][n]
__device__ float g_kpd[BATCH * NSLICE * NPTS * KNN];
__device__ int   g_kpi[BATCH * NSLICE * NPTS * KNN];

// ---------------- f32x2 helpers ----------------
__device__ __forceinline__ u64 bcast2(float a) {
    u64 r; asm("mov.b64 %0, {%1, %1};" : "=l"(r) : "f"(a)); return r;
}
__device__ __forceinline__ void fma2(u64& d, u64 a, u64 b) {
    asm("fma.rn.f32x2 %0, %1, %2, %0;" : "+l"(d) : "l"(a), "l"(b));
}

// ---------------- weight prep ----------------
__global__ void prep_w(const float* __restrict__ W1, const float* __restrict__ W2,
                       float* __restrict__ Wc1, float* __restrict__ Wc2) {
    int i = blockIdx.x * blockDim.x + threadIdx.x;
    if (i < 256 * 128) {
        int o = i / 128, c = i % 128;
        if (o < 128) Wc1[i] = W1[o * 256 + c] - W1[o * 256 + 128 + c];
        else         Wc1[i] = W1[(o - 128) * 256 + 128 + c];
    }
    if (i < 512 * 128) {
        int o = i / 128, c = i % 128;
        if (o < 256) Wc2[i] = W2[o * 256 + c] - W2[o * 256 + 128 + c];
        else         Wc2[i] = W2[(o - 256) * 256 + 128 + c];
    }
}

// ---------------- copy x0 halves into xcat rows [0,128) ----------------
__global__ void copy_x0(const float4* __restrict__ f, float4* __restrict__ xcat, int b0) {
    int i = blockIdx.x * blockDim.x + threadIdx.x;
    const int per = CCH * NPTS / 4;
    if (i >= 2 * per) return;
    int b = b0 + i / per, r = i % per;
    xcat[(size_t)b * (512 * NPTS / 4) + r] = f[(size_t)b * per + r];
}

// ---------------- KNN pass1: 2x2048 slices, batched-distance ILP ----------------
__global__ __launch_bounds__(128)
void knn_part(const float* __restrict__ coords,
              float* __restrict__ pd, int* __restrict__ pi) {
    int b = blockIdx.z, s = blockIdx.y;
    int n = blockIdx.x * 128 + threadIdx.x;
    const float* cb = coords + (size_t)b * 3 * NPTS;
    __shared__ float4 sc[SLICE];                 // 32 KB
    int base = s * SLICE;
    for (int j = threadIdx.x; j < SLICE; j += 128) {
        float x = cb[base + j], y = cb[NPTS + base + j], z = cb[2 * NPTS + base + j];
        sc[j] = make_float4(x, y, z, x * x + y * y + z * z);
    }
    __syncthreads();
    float qx = cb[n], qy = cb[NPTS + n], qz = cb[2 * NPTS + n];
    float qs = qx * qx + qy * qy + qz * qz;

    float dist[KNN]; int ind[KNN];
#pragma unroll
    for (int i = 0; i < KNN; i++) { dist[i] = 3.4e38f; ind[i] = 0x7fffffff; }

    for (int j0 = 0; j0 < SLICE; j0 += 8) {
        // phase 1: 8 independent distances (8 LDS.128 in flight, MLP=8)
        float d[8];
#pragma unroll
        for (int e = 0; e < 8; e++) {
            float4 c = sc[j0 + e];
            float dot = qx * c.x + qy * c.y + qz * c.z;
            d[e] = fmaxf(fmaf(-2.f, dot, qs + c.w), 1e-12f);
        }
        // phase 2: sequential threshold checks + register-only inserts
#pragma unroll
        for (int e = 0; e < 8; e++) {
            int jj = base + j0 + e;
            if (d[e] < dist[KNN - 1] && jj != n) {
                dist[KNN - 1] = d[e]; ind[KNN - 1] = jj;
#pragma unroll
                for (int i = KNN - 1; i > 0; i--) {
                    bool sw = dist[i] < dist[i - 1];
                    float td = sw ? dist[i - 1] : dist[i];
                    int   ti = sw ? ind[i - 1]  : ind[i];
                    dist[i - 1] = sw ? dist[i] : dist[i - 1];
                    ind[i - 1]  = sw ? ind[i]  : ind[i - 1];
                    dist[i] = td; ind[i] = ti;
                }
            }
        }
    }
    size_t off = ((size_t)(b * NSLICE + s) * NPTS + n) * KNN;
#pragma unroll
    for (int i = 0; i < KNN; i++) { pd[off + i] = dist[i]; pi[off + i] = ind[i]; }
}

// ---------------- KNN merge: 2 sorted lists -> final 10, transposed output ----------------
__global__ void knn_merge(const float* __restrict__ pd, const int* __restrict__ pi,
                          int* __restrict__ idt) {
    int t = blockIdx.x * 256 + threadIdx.x;
    if (t >= RTOT) return;
    int b = t >> 12, n = t & (NPTS - 1);
    const float* pdp[NSLICE]; const int* pip[NSLICE]; int pos[NSLICE] = {0, 0};
#pragma unroll
    for (int s = 0; s < NSLICE; s++) {
        size_t off = ((size_t)(b * NSLICE + s) * NPTS + n) * KNN;
        pdp[s] = pd + off; pip[s] = pi + off;
    }
#pragma unroll
    for (int r = 0; r < KNN; r++) {
        float d0 = pdp[0][pos[0]], d1 = pdp[1][pos[1]];
        int i0 = pip[0][pos[0]], i1 = pip[1][pos[1]];
        bool take0 = (d0 < d1) || (d0 == d1 && i0 < i1);
        idt[((size_t)b * KNN + r) * NPTS + n] = take0 ? i0 : i1;
        if (take0) pos[0]++; else pos[1]++;
    }
}

// ---------------- GEMM tile (FFMA2, proven): 128x128, 8x8 micro ----------------
__device__ __forceinline__ void gemm_tile(const float* __restrict__ A, int lda,
                                          const float* __restrict__ Xb,
                                          float* __restrict__ Ob, int Kd,
                                          int n0, int m0, bool accum) {
    const int NN = NPTS;
    __shared__ float As[16][132];
    __shared__ float Xs[16][132];

    int tid = threadIdx.x;
    int tr = tid & 15;
    int tm = tid >> 4;
    u64 acc2[8][4];
#pragma unroll
    for (int i = 0; i < 8; i++)
#pragma unroll
        for (int p = 0; p < 4; p++) acc2[i][p] = 0ull;

    for (int k0 = 0; k0 < Kd; k0 += 16) {
#pragma unroll
        for (int t = 0; t < 2; t++) {
            int f = tid * 2 + t;
            int rr = f >> 2, kc = (f & 3) * 4;
            float4 v = *(const float4*)&A[(size_t)(m0 + rr) * lda + k0 + kc];
            As[kc + 0][rr] = v.x; As[kc + 1][rr] = v.y;
            As[kc + 2][rr] = v.z; As[kc + 3][rr] = v.w;
        }
#pragma unroll
        for (int t = 0; t < 2; t++) {
            int f = tid * 2 + t;
            int kk = f >> 5, nc = (f & 31) * 4;
            *(float4*)&Xs[kk][nc] =
                *(const float4*)&Xb[(size_t)(k0 + kk) * NN + n0 + nc];
        }
        __syncthreads();
#pragma unroll
        for (int kk = 0; kk < 16; kk++) {
            float am[8];
            float4 x0 = *(const float4*)&Xs[kk][tr * 4];
            float4 x1 = *(const float4*)&Xs[kk][tr * 4 + 64];
            *(float4*)&am[0] = *(const float4*)&As[kk][tm * 4];
            *(float4*)&am[4] = *(const float4*)&As[kk][tm * 4 + 64];
            u64 xp[4];
            xp[0] = ((const u64*)&x0)[0]; xp[1] = ((const u64*)&x0)[1];
            xp[2] = ((const u64*)&x1)[0]; xp[3] = ((const u64*)&x1)[1];
#pragma unroll
            for (int i = 0; i < 8; i++) {
                u64 ab = bcast2(am[i]);
                fma2(acc2[i][0], ab, xp[0]);
                fma2(acc2[i][1], ab, xp[1]);
                fma2(acc2[i][2], ab, xp[2]);
                fma2(acc2[i][3], ab, xp[3]);
            }
        }
        __syncthreads();
    }
#pragma unroll
    for (int h = 0; h < 2; h++) {
#pragma unroll
        for (int i = 0; i < 4; i++) {
            int m = m0 + tm * 4 + i + h * 64;
            float* orow = Ob + (size_t)m * NN + n0;
            float4 v0, v1;
            ((u64*)&v0)[0] = acc2[h * 4 + i][0]; ((u64*)&v0)[1] = acc2[h * 4 + i][1];
            ((u64*)&v1)[0] = acc2[h * 4 + i][2]; ((u64*)&v1)[1] = acc2[h * 4 + i][3];
            if (accum) {
                float4 o0 = *(const float4*)&orow[tr * 4];
                float4 o1 = *(const float4*)&orow[tr * 4 + 64];
                v0.x += o0.x; v0.y += o0.y; v0.z += o0.z; v0.w += o0.w;
                v1.x += o1.x; v1.y += o1.y; v1.z += o1.z; v1.w += o1.w;
            }
            *(float4*)&orow[tr * 4] = v0;
            *(float4*)&orow[tr * 4 + 64] = v1;
        }
    }
}

// ---------------- generic GEMM launcher kernel ----------------
__global__ __launch_bounds__(256)
void gemm_full(const float* __restrict__ A, int lda,
               const float* __restrict__ X,
               float* __restrict__ O, int orows, int Kd, int accum) {
    int n0 = blockIdx.x * 128, m0 = blockIdx.y * 128, b = blockIdx.z;
    gemm_tile(A, lda, X + (size_t)b * 512 * NPTS,
              O + (size_t)b * orows * NPTS, Kd, n0, m0, accum != 0);
}

// ---------------- EdgeConv epilogue v4: 2 channels/block, register max ----------------
__global__ __launch_bounds__(256)
void edge_epilogue(const float* __restrict__ UV, const int* __restrict__ idt,
                   float* __restrict__ xcat, int Ch, int rowsPerBatch, int outRow0) {
    int o0 = blockIdx.x * 2, b = blockIdx.y, tid = threadIdx.x;
    const float* U0 = UV + ((size_t)b * rowsPerBatch + o0) * NPTS;
    const float* U1 = U0 + NPTS;
    const float* V0 = UV + ((size_t)b * rowsPerBatch + Ch + o0) * NPTS;
    const float* V1 = V0 + NPTS;
    const int* it = idt + (size_t)b * KNN * NPTS;
    float* op0 = xcat + ((size_t)b * 512 + outRow0 + o0) * NPTS;
    float* op1 = op0 + NPTS;

    __shared__ float  sV0[NPTS], sV1[NPTS];
    __shared__ double sr0[256], sq0[256], sr1[256], sq1[256];
    __shared__ float  smu0, srstd0, smu1, srstd1;

    {
        const float4* a = (const float4*)V0; float4* d0 = (float4*)sV0;
        const float4* c = (const float4*)V1; float4* d1 = (float4*)sV1;
#pragma unroll
        for (int i = 0; i < 4; i++) {
            d0[tid + i * 256] = a[tid + i * 256];
            d1[tid + i * 256] = c[tid + i * 256];
        }
    }
    __syncthreads();

    float m0[16], m1[16];
    double S0 = 0.0, Q0 = 0.0, S1 = 0.0, Q1 = 0.0;
#pragma unroll
    for (int itn = 0; itn < 16; itn++) {
        int n = tid + itn * 256;
        float u0 = U0[n], u1 = U1[n];
        float a0 = -3.4e38f, a1 = -3.4e38f;
        float p0 = 0.f, q0 = 0.f, p1 = 0.f, q1 = 0.f;
#pragma unroll
        for (int kk = 0; kk < KNN; kk++) {
            int j = it[kk * NPTS + n];
            float y0 = u0 + sV0[j];
            float y1 = u1 + sV1[j];
            a0 = fmaxf(a0, y0); p0 += y0; q0 += y0 * y0;
            a1 = fmaxf(a1, y1); p1 += y1; q1 += y1 * y1;
        }
        m0[itn] = a0; m1[itn] = a1;
        S0 += (double)p0; Q0 += (double)q0;
        S1 += (double)p1; Q1 += (double)q1;
    }
    sr0[tid] = S0; sq0[tid] = Q0; sr1[tid] = S1; sq1[tid] = Q1;
    __syncthreads();
    for (int st = 128; st > 0; st >>= 1) {
        if (tid < st) {
            sr0[tid] += sr0[tid + st]; sq0[tid] += sq0[tid + st];
            sr1[tid] += sr1[tid + st]; sq1[tid] += sq1[tid + st];
        }
        __syncthreads();
    }
    if (tid == 0) {
        double cnt = (double)NPTS * KNN;
        double mu  = sr0[0] / cnt;
        double var = sq0[0] / cnt - mu * mu;
        smu0 = (float)mu; srstd0 = (float)(1.0 / sqrt(var + 1e-5));
        mu  = sr1[0] / cnt;
        var = sq1[0] / cnt - mu * mu;
        smu1 = (float)mu; srstd1 = (float)(1.0 / sqrt(var + 1e-5));
    }
    __syncthreads();
    float mu0 = smu0, r0 = srstd0, mu1 = smu1, r1 = srstd1;
#pragma unroll
    for (int itn = 0; itn < 16; itn++) {
        int n = tid + itn * 256;
        float v0 = (m0[itn] - mu0) * r0;
        float v1 = (m1[itn] - mu1) * r1;
        op0[n] = v0 >= 0.f ? v0 : 0.2f * v0;
        op1[n] = v1 >= 0.f ? v1 : 0.2f * v1;
    }
}

// ---------------- final instance-norm (over N) + lrelu ----------------
__global__ void norm_epilogue(const float* __restrict__ Y, float* __restrict__ out) {
    int o = blockIdx.x, b = blockIdx.y, tid = threadIdx.x;
    const float* y = Y + ((size_t)b * CCH + o) * NPTS;
    float* op = out + ((size_t)b * CCH + o) * NPTS;

    __shared__ double sred[256], s2red[256];
    __shared__ float  smu, srstd;

    double s = 0.0, s2 = 0.0;
    for (int n = tid; n < NPTS; n += 256) {
        float v = y[n];
        s += (double)v; s2 += (double)v * (double)v;
    }
    sred[tid] = s; s2red[tid] = s2;
    __syncthreads();
    for (int st = 128; st > 0; st >>= 1) {
        if (tid < st) { sred[tid] += sred[tid + st]; s2red[tid] += s2red[tid + st]; }
        __syncthreads();
    }
    if (tid == 0) {
        double cnt = (double)NPTS;
        double mu  = sred[0] / cnt;
        double var = s2red[0] / cnt - mu * mu;
        smu   = (float)mu;
        srstd = (float)(1.0 / sqrt(var + 1e-5));
    }
    __syncthreads();
    float mu = smu, r = srstd;
    for (int n = tid; n < NPTS; n += 256) {
        float v = (y[n] - mu) * r;
        op[n] = v >= 0.f ? v : 0.2f * v;
    }
}

// ---------------- launch: graph-forked parallel branches (static handles) ----------------
extern "C" void kernel_launch(void* const* d_in, const int* in_sizes, int n_in,
                              void* d_out, int out_size) {
    const float* coords = (const float*)d_in[0];
    const float* feats  = (const float*)d_in[1];
    const float* W1     = (const float*)d_in[2];
    const float* W2     = (const float*)d_in[3];
    const float* W3     = (const float*)d_in[4];
    float* out = (float*)d_out;

    float *Wc1, *Wc2, *UV1, *UV2, *xcat, *y3, *kpd;
    int *idt, *kpi;
    cudaGetSymbolAddress((void**)&Wc1,  g_Wc1);
    cudaGetSymbolAddress((void**)&Wc2,  g_Wc2);
    cudaGetSymbolAddress((void**)&UV1,  g_UV1);
    cudaGetSymbolAddress((void**)&UV2,  g_UV2);
    cudaGetSymbolAddress((void**)&xcat, g_xcat);
    cudaGetSymbolAddress((void**)&y3,   g_y3);
    cudaGetSymbolAddress((void**)&idt,  g_idt);
    cudaGetSymbolAddress((void**)&kpd,  g_kpd);
    cudaGetSymbolAddress((void**)&kpi,  g_kpi);

    // Streams/events created EXACTLY ONCE (first call, pre-capture) and never
    // destroyed -> post-teardown free memory matches the pre-capture baseline.
    static cudaStream_t sB = nullptr, sC = nullptr;
    static cudaEvent_t eF1, eB, eF2, eC;
    static bool inited = false;
    if (!inited) {
        cudaStreamCreateWithFlags(&sB, cudaStreamNonBlocking);
        cudaStreamCreateWithFlags(&sC, cudaStreamNonBlocking);
        cudaEventCreateWithFlags(&eF1, cudaEventDisableTiming);
        cudaEventCreateWithFlags(&eB,  cudaEventDisableTiming);
        cudaEventCreateWithFlags(&eF2, cudaEventDisableTiming);
        cudaEventCreateWithFlags(&eC,  cudaEventDisableTiming);
        inited = true;
    }

    const int perHalf = 2 * CCH * NPTS / 4;

    // ---- fork branch B off the main stream ----
    cudaEventRecord(eF1, 0);
    cudaStreamWaitEvent(sB, eF1, 0);

    // branch B prep first; knn_part is the 4th submitted kernel (profiled slot)
    prep_w<<<256, 256, 0, sB>>>(W1, W2, Wc1, Wc2);
    copy_x0<<<(perHalf + 255) / 256, 256, 0, sB>>>((const float4*)feats, (float4*)xcat, 0);
    copy_x0<<<(perHalf + 255) / 256, 256, 0, sB>>>((const float4*)feats, (float4*)xcat, 2);

    // main stream: KNN chain (critical path, concurrent with branch B)
    knn_part<<<dim3(NPTS / 128, NSLICE, BATCH), 128>>>(coords, kpd, kpi);

    // branch B: gemm1 + gemm3a
    gemm_full<<<dim3(32, 2, BATCH), 256, 0, sB>>>(Wc1, 128, xcat, UV1, 256, 128, 0);
    gemm_full<<<dim3(32, 1, BATCH), 256, 0, sB>>>(W3, 512, xcat, y3, 128, 128, 0);   // y3 = W3a@x0

    // main: merge
    knn_merge<<<RTOT / 256, 256>>>(kpd, kpi, idt);

    // join B -> main
    cudaEventRecord(eB, sB);
    cudaStreamWaitEvent(0, eB, 0);

    // main: edge1 (needs idt + UV1)
    edge_epilogue<<<dim3(128 / 2, BATCH), 256>>>(UV1, idt, xcat, 128, 256, 128);

    // ---- fork branch C (gemm3b needs x1 only) ----
    cudaEventRecord(eF2, 0);
    cudaStreamWaitEvent(sC, eF2, 0);
    gemm_full<<<dim3(32, 1, BATCH), 256, 0, sC>>>(W3 + 128, 512, xcat + (size_t)128 * NPTS,
                                                  y3, 128, 128, 1);  // y3 += W3b@x1

    // main: gemm2 -> edge2
    gemm_full<<<dim3(32, 4, BATCH), 256>>>(Wc2, 128, xcat + (size_t)128 * NPTS, UV2, 512, 128, 0);
    edge_epilogue<<<dim3(256 / 2, BATCH), 256>>>(UV2, idt, xcat, 256, 512, 256);

    // join C -> main
    cudaEventRecord(eC, sC);
    cudaStreamWaitEvent(0, eC, 0);

    // main: gemm3c (y3 += W3c@x2, K=256) -> final norm
    gemm_full<<<dim3(32, 1, BATCH), 256>>>(W3 + 256, 512, xcat + (size_t)256 * NPTS, y3, 128, 256, 1);
    norm_epilogue<<<dim3(128, BATCH), 256>>>(y3, out);
}